// round 1
// baseline (speedup 1.0000x reference)
#include <cuda_runtime.h>
#include <math.h>

#define N_NODES 30000
#define N_EDGES 480000
#define E_TOT   (N_EDGES + N_NODES)   // 510000 (self-loops appended)
#define NEG_SLOPE 0.2f

// ---------------- device scratch (static, no allocation) ----------------
__device__ int   g_flag32;                 // 1 => edge_index is int32
__device__ int   g_deg[N_NODES];
__device__ int   g_rowptr[N_NODES + 1];
__device__ int   g_cursor[N_NODES];
__device__ int   g_src[E_TOT];
__device__ int   g_dst[E_TOT];
__device__ int   g_srcsorted[E_TOT];
__device__ float g_h1[N_NODES * 128];
__device__ float g_as1[N_NODES * 8];
__device__ float g_ad1[N_NODES * 8];
__device__ float g_x2[N_NODES * 128];
__device__ float g_h2[N_NODES * 64];
__device__ float g_as2[N_NODES];
__device__ float g_ad2[N_NODES];
__device__ float g_w[E_TOT * 8];           // per-edge softmax numerators (sorted order)

// ---------------- edge dtype detection ----------------
// If int64: words[2i+1] are high halves of values < 30000 -> all zero.
// If int32: odd words are random dst/src values -> some nonzero (w.p. 1).
// Only reads the first 2*N_EDGES 32-bit words (guaranteed present either way).
__global__ void k_detect(const unsigned int* __restrict__ w) {
    unsigned int acc = 0;
    int stride = gridDim.x * blockDim.x;
    for (int i = (blockIdx.x * blockDim.x + threadIdx.x) * 2 + 1;
         i < 2 * N_EDGES; i += 2 * stride)
        acc |= w[i];
    if (acc) atomicOr(&g_flag32, 1);
}

// convert to int src/dst (append self-loops) + histogram degrees by dst
__global__ void k_convert(const void* __restrict__ edges) {
    int i = blockIdx.x * blockDim.x + threadIdx.x;
    if (i >= E_TOT) return;
    int s, d;
    if (i < N_EDGES) {
        if (g_flag32) {
            const int* p = (const int*)edges;
            s = p[i]; d = p[N_EDGES + i];
        } else {
            const long long* p = (const long long*)edges;
            s = (int)p[i]; d = (int)p[N_EDGES + i];
        }
    } else {
        s = d = i - N_EDGES;
    }
    g_src[i] = s; g_dst[i] = d;
    atomicAdd(&g_deg[d], 1);
}

// single-block exclusive scan (30000 elements)
__global__ void k_scan() {
    __shared__ int ss[1024];
    const int CH = (N_NODES + 1023) / 1024;   // 30
    int t = threadIdx.x;
    int base = t * CH;
    int s = 0;
    for (int i = 0; i < CH; i++) {
        int idx = base + i;
        if (idx < N_NODES) s += g_deg[idx];
    }
    ss[t] = s;
    __syncthreads();
    for (int off = 1; off < 1024; off <<= 1) {
        int v = (t >= off) ? ss[t - off] : 0;
        __syncthreads();
        ss[t] += v;
        __syncthreads();
    }
    int run = (t == 0) ? 0 : ss[t - 1];
    for (int i = 0; i < CH; i++) {
        int idx = base + i;
        if (idx < N_NODES) {
            g_rowptr[idx] = run;
            g_cursor[idx] = run;
            run += g_deg[idx];
        }
    }
    if (t == 0) g_rowptr[N_NODES] = E_TOT;
}

__global__ void k_scatter() {
    int i = blockIdx.x * blockDim.x + threadIdx.x;
    if (i >= E_TOT) return;
    int d = g_dst[i];
    int pos = atomicAdd(&g_cursor[d], 1);
    g_srcsorted[pos] = g_src[i];
}

// ---------------- register-tiled SGEMM: H[M,NOUT] = X[M,128] @ W[128,NOUT] ----------------
template <int NOUT, int TY, int NPT>
__global__ void k_gemm(const float* __restrict__ X, const float* __restrict__ W,
                       float* __restrict__ H) {
    constexpr int K  = 128;
    constexpr int TX = NOUT / 4;
    constexpr int MB = TY * NPT;              // nodes per block
    __shared__ float xs[MB][K];

    int tile0 = blockIdx.x * MB;
    int tid = threadIdx.y * TX + threadIdx.x;
    constexpr int NLOAD = MB * K / 4;
    for (int idx = tid; idx < NLOAD; idx += TX * TY) {
        int r = idx / (K / 4), c = idx % (K / 4);
        float4 v = make_float4(0.f, 0.f, 0.f, 0.f);
        int node = tile0 + r;
        if (node < N_NODES) v = ((const float4*)X)[node * (K / 4) + c];
        *(float4*)&xs[r][c * 4] = v;
    }
    __syncthreads();

    float4 acc[NPT];
#pragma unroll
    for (int p = 0; p < NPT; p++) acc[p] = make_float4(0.f, 0.f, 0.f, 0.f);
    int jx = threadIdx.x * 4;
    const float* Wp = W + jx;

#pragma unroll 4
    for (int k = 0; k < K; k++) {
        float4 w = *(const float4*)(Wp + k * NOUT);
#pragma unroll
        for (int p = 0; p < NPT; p++) {
            float xv = xs[threadIdx.y * NPT + p][k];
            acc[p].x += w.x * xv; acc[p].y += w.y * xv;
            acc[p].z += w.z * xv; acc[p].w += w.w * xv;
        }
    }
#pragma unroll
    for (int p = 0; p < NPT; p++) {
        int node = tile0 + threadIdx.y * NPT + p;
        if (node < N_NODES) *(float4*)&H[node * NOUT + jx] = acc[p];
    }
}

// ---------------- per-node attention coefficients ----------------
__global__ void k_alpha1(const float* __restrict__ asrc, const float* __restrict__ adst) {
    int t = blockIdx.x * blockDim.x + threadIdx.x;
    if (t >= N_NODES * 8) return;
    int n = t >> 3, h = t & 7;
    const float4* hp = (const float4*)&g_h1[n * 128 + h * 16];
    const float4* ap = (const float4*)&asrc[h * 16];
    const float4* bp = (const float4*)&adst[h * 16];
    float s = 0.f, d = 0.f;
#pragma unroll
    for (int i = 0; i < 4; i++) {
        float4 hv = hp[i], av = ap[i], bv = bp[i];
        s += hv.x * av.x + hv.y * av.y + hv.z * av.z + hv.w * av.w;
        d += hv.x * bv.x + hv.y * bv.y + hv.z * bv.z + hv.w * bv.w;
    }
    g_as1[t] = s; g_ad1[t] = d;
}

__global__ void k_alpha2(const float* __restrict__ asrc, const float* __restrict__ adst) {
    int n = blockIdx.x * blockDim.x + threadIdx.x;
    if (n >= N_NODES) return;
    const float4* hp = (const float4*)&g_h2[n * 64];
    float s = 0.f, d = 0.f;
#pragma unroll
    for (int i = 0; i < 16; i++) {
        float4 hv = hp[i];
        float4 av = ((const float4*)asrc)[i];
        float4 bv = ((const float4*)adst)[i];
        s += hv.x * av.x + hv.y * av.y + hv.z * av.z + hv.w * av.w;
        d += hv.x * bv.x + hv.y * bv.y + hv.z * bv.z + hv.w * bv.w;
    }
    g_as2[n] = s; g_ad2[n] = d;
}

// ---------------- layer-1 softmax+aggregate (warp per dst) ----------------
// out: g_x2 = elu(segment_sum(h1[src] * alpha) + b1)
__global__ void k_agg1(const float* __restrict__ b1) {
    int gw = (blockIdx.x * blockDim.x + threadIdx.x) >> 5;
    int lane = threadIdx.x & 31;
    if (gw >= N_NODES) return;
    int beg = g_rowptr[gw], end = g_rowptr[gw + 1];

    float ad[8];
    {
        const float4* p = (const float4*)&g_ad1[gw * 8];
        float4 a = p[0], b = p[1];
        ad[0] = a.x; ad[1] = a.y; ad[2] = a.z; ad[3] = a.w;
        ad[4] = b.x; ad[5] = b.y; ad[6] = b.z; ad[7] = b.w;
    }

    float mx[8];
#pragma unroll
    for (int h = 0; h < 8; h++) mx[h] = -1e30f;
    for (int e = beg + lane; e < end; e += 32) {
        int s = g_srcsorted[e];
        const float4* p = (const float4*)&g_as1[s * 8];
        float4 a = p[0], b = p[1];
        float as[8] = {a.x, a.y, a.z, a.w, b.x, b.y, b.z, b.w};
#pragma unroll
        for (int h = 0; h < 8; h++) {
            float v = as[h] + ad[h];
            v = v > 0.f ? v : NEG_SLOPE * v;
            mx[h] = fmaxf(mx[h], v);
        }
    }
#pragma unroll
    for (int o = 16; o; o >>= 1)
#pragma unroll
        for (int h = 0; h < 8; h++)
            mx[h] = fmaxf(mx[h], __shfl_xor_sync(0xffffffffu, mx[h], o));

    float sm[8];
#pragma unroll
    for (int h = 0; h < 8; h++) sm[h] = 0.f;
    for (int e = beg + lane; e < end; e += 32) {
        int s = g_srcsorted[e];
        const float4* p = (const float4*)&g_as1[s * 8];
        float4 a = p[0], b = p[1];
        float as[8] = {a.x, a.y, a.z, a.w, b.x, b.y, b.z, b.w};
        float wv[8];
#pragma unroll
        for (int h = 0; h < 8; h++) {
            float v = as[h] + ad[h];
            v = v > 0.f ? v : NEG_SLOPE * v;
            float w = __expf(v - mx[h]);
            sm[h] += w;
            wv[h] = w;
        }
        float4* wp = (float4*)&g_w[e * 8];
        wp[0] = make_float4(wv[0], wv[1], wv[2], wv[3]);
        wp[1] = make_float4(wv[4], wv[5], wv[6], wv[7]);
    }
#pragma unroll
    for (int o = 16; o; o >>= 1)
#pragma unroll
        for (int h = 0; h < 8; h++)
            sm[h] += __shfl_xor_sync(0xffffffffu, sm[h], o);

    int head = lane >> 2;                 // 4 lanes per head (dh=16 -> 4 floats/lane)
    float hinv = 1.f / (sm[head] + 1e-16f);
    int col = lane * 4;
    float4 acc = make_float4(0.f, 0.f, 0.f, 0.f);
    for (int e = beg; e < end; e++) {
        int s = g_srcsorted[e];
        float w = g_w[e * 8 + head] * hinv;
        float4 hv = *(const float4*)&g_h1[s * 128 + col];
        acc.x += hv.x * w; acc.y += hv.y * w;
        acc.z += hv.z * w; acc.w += hv.w * w;
    }
    float4 bb = *(const float4*)&b1[col];
    float o0 = acc.x + bb.x, o1 = acc.y + bb.y, o2 = acc.z + bb.z, o3 = acc.w + bb.w;
    o0 = o0 > 0.f ? o0 : expm1f(o0);
    o1 = o1 > 0.f ? o1 : expm1f(o1);
    o2 = o2 > 0.f ? o2 : expm1f(o2);
    o3 = o3 > 0.f ? o3 : expm1f(o3);
    *(float4*)&g_x2[gw * 128 + col] = make_float4(o0, o1, o2, o3);
}

// ---------------- layer-2 softmax+aggregate + bias + elu + log_softmax ----------------
__global__ void k_agg2(const float* __restrict__ b2, float* __restrict__ out) {
    int gw = (blockIdx.x * blockDim.x + threadIdx.x) >> 5;
    int lane = threadIdx.x & 31;
    if (gw >= N_NODES) return;
    int beg = g_rowptr[gw], end = g_rowptr[gw + 1];
    float ad = g_ad2[gw];

    float mx = -1e30f;
    for (int e = beg + lane; e < end; e += 32) {
        float v = g_as2[g_srcsorted[e]] + ad;
        v = v > 0.f ? v : NEG_SLOPE * v;
        mx = fmaxf(mx, v);
    }
#pragma unroll
    for (int o = 16; o; o >>= 1) mx = fmaxf(mx, __shfl_xor_sync(0xffffffffu, mx, o));

    float sm = 0.f;
    for (int e = beg + lane; e < end; e += 32) {
        float v = g_as2[g_srcsorted[e]] + ad;
        v = v > 0.f ? v : NEG_SLOPE * v;
        float w = __expf(v - mx);
        sm += w;
        g_w[e] = w;
    }
#pragma unroll
    for (int o = 16; o; o >>= 1) sm += __shfl_xor_sync(0xffffffffu, sm, o);
    float inv = 1.f / (sm + 1e-16f);

    int col = lane * 2;
    float a0 = 0.f, a1 = 0.f;
    for (int e = beg; e < end; e++) {
        int s = g_srcsorted[e];
        float w = g_w[e] * inv;
        float2 hv = *(const float2*)&g_h2[s * 64 + col];
        a0 += hv.x * w; a1 += hv.y * w;
    }
    float v0 = a0 + b2[col], v1 = a1 + b2[col + 1];
    v0 = v0 > 0.f ? v0 : expm1f(v0);
    v1 = v1 > 0.f ? v1 : expm1f(v1);

    // log_softmax over the 64 dims of this warp
    float m = fmaxf(v0, v1);
#pragma unroll
    for (int o = 16; o; o >>= 1) m = fmaxf(m, __shfl_xor_sync(0xffffffffu, m, o));
    float es = expf(v0 - m) + expf(v1 - m);
#pragma unroll
    for (int o = 16; o; o >>= 1) es += __shfl_xor_sync(0xffffffffu, es, o);
    float lse = m + logf(es);
    *(float2*)&out[gw * 64 + col] = make_float2(v0 - lse, v1 - lse);
}

// ---------------- launch ----------------
extern "C" void kernel_launch(void* const* d_in, const int* in_sizes, int n_in,
                              void* d_out, int out_size) {
    const float* x      = (const float*)d_in[0];
    const void*  ei     = d_in[1];
    const float* W1     = (const float*)d_in[2];
    const float* a_src1 = (const float*)d_in[3];
    const float* a_dst1 = (const float*)d_in[4];
    const float* b1     = (const float*)d_in[5];
    const float* W2     = (const float*)d_in[6];
    const float* a_src2 = (const float*)d_in[7];
    const float* a_dst2 = (const float*)d_in[8];
    const float* b2     = (const float*)d_in[9];
    float* out = (float*)d_out;

    void *p_flag, *p_deg, *p_h1, *p_x2, *p_h2;
    cudaGetSymbolAddress(&p_flag, g_flag32);
    cudaGetSymbolAddress(&p_deg, g_deg);
    cudaGetSymbolAddress(&p_h1, g_h1);
    cudaGetSymbolAddress(&p_x2, g_x2);
    cudaGetSymbolAddress(&p_h2, g_h2);

    cudaMemsetAsync(p_flag, 0, sizeof(int));
    cudaMemsetAsync(p_deg, 0, N_NODES * sizeof(int));

    k_detect<<<256, 256>>>((const unsigned int*)ei);
    k_convert<<<(E_TOT + 255) / 256, 256>>>(ei);
    k_scan<<<1, 1024>>>();
    k_scatter<<<(E_TOT + 255) / 256, 256>>>();

    // layer 1
    k_gemm<128, 8, 4><<<(N_NODES + 31) / 32, dim3(32, 8)>>>(x, W1, (float*)p_h1);
    k_alpha1<<<(N_NODES * 8 + 255) / 256, 256>>>(a_src1, a_dst1);
    k_agg1<<<(N_NODES * 32 + 255) / 256, 256>>>(b1);

    // layer 2
    k_gemm<64, 16, 4><<<(N_NODES + 63) / 64, dim3(16, 16)>>>((const float*)p_x2, W2, (float*)p_h2);
    k_alpha2<<<(N_NODES + 255) / 256, 256>>>(a_src2, a_dst2);
    k_agg2<<<(N_NODES * 32 + 255) / 256, 256>>>(b2, out);
}

// round 2
// speedup vs baseline: 1.3148x; 1.3148x over previous
#include <cuda_runtime.h>
#include <math.h>

#define N_NODES 30000
#define N_EDGES 480000
#define E_TOT   (N_EDGES + N_NODES)   // 510000 (self-loops appended)
#define NEG_SLOPE 0.2f

// ---------------- device scratch (static, no allocation) ----------------
__device__ int   g_flag32;                 // 1 => edge_index is int32
__device__ int   g_deg[N_NODES];
__device__ int   g_rowptr[N_NODES + 1];
__device__ int   g_src[E_TOT];
__device__ int   g_dst[E_TOT];
__device__ int   g_rank[E_TOT];
__device__ int   g_srcsorted[E_TOT];
__device__ float g_h1[N_NODES * 128];
__device__ float g_as1[N_NODES * 8];
__device__ float g_ad1[N_NODES * 8];
__device__ float g_x2[N_NODES * 128];
__device__ float g_h2[N_NODES * 64];
__device__ float g_as2[N_NODES];
__device__ float g_ad2[N_NODES];

// ---------------- edge dtype detection ----------------
// If int64: odd 32-bit words are high halves of values < 30000 -> all zero.
// If int32: odd words are random indices -> some nonzero (w.p. 1).
__global__ void k_detect(const unsigned int* __restrict__ w) {
    unsigned int acc = 0;
    int stride = gridDim.x * blockDim.x;
    for (int i = (blockIdx.x * blockDim.x + threadIdx.x) * 2 + 1;
         i < 2 * N_EDGES; i += 2 * stride)
        acc |= w[i];
    if (acc) atomicOr(&g_flag32, 1);
}

// convert to int src/dst (append self-loops) + histogram degrees by dst,
// capturing each edge's rank within its destination bucket.
__global__ void k_convert(const void* __restrict__ edges) {
    int i = blockIdx.x * blockDim.x + threadIdx.x;
    if (i >= E_TOT) return;
    int s, d;
    if (i < N_EDGES) {
        if (g_flag32) {
            const int* p = (const int*)edges;
            s = p[i]; d = p[N_EDGES + i];
        } else {
            const long long* p = (const long long*)edges;
            s = (int)p[i]; d = (int)p[N_EDGES + i];
        }
    } else {
        s = d = i - N_EDGES;
    }
    g_src[i] = s; g_dst[i] = d;
    g_rank[i] = atomicAdd(&g_deg[d], 1);
}

// single-block exclusive scan (30000 elements)
__global__ void k_scan() {
    __shared__ int ss[1024];
    const int CH = (N_NODES + 1023) / 1024;   // 30
    int t = threadIdx.x;
    int base = t * CH;
    int s = 0;
    for (int i = 0; i < CH; i++) {
        int idx = base + i;
        if (idx < N_NODES) s += g_deg[idx];
    }
    ss[t] = s;
    __syncthreads();
    for (int off = 1; off < 1024; off <<= 1) {
        int v = (t >= off) ? ss[t - off] : 0;
        __syncthreads();
        ss[t] += v;
        __syncthreads();
    }
    int run = (t == 0) ? 0 : ss[t - 1];
    for (int i = 0; i < CH; i++) {
        int idx = base + i;
        if (idx < N_NODES) {
            g_rowptr[idx] = run;
            run += g_deg[idx];
        }
    }
    if (t == 0) g_rowptr[N_NODES] = E_TOT;
}

// atomic-free scatter using precomputed ranks
__global__ void k_scatter() {
    int i = blockIdx.x * blockDim.x + threadIdx.x;
    if (i >= E_TOT) return;
    g_srcsorted[g_rowptr[g_dst[i]] + g_rank[i]] = g_src[i];
}

// ---------------- register-tiled SGEMM + fused alpha epilogue ----------------
// H[M,NOUT] = X[M,128] @ W[128,NOUT]; also as/ad[n,h] = <H_row_head, a_src/a_dst>
// HEADS heads of NOUT/HEADS cols each; per-thread cols (4) lie within one head.
template <int NOUT, int TY, int NPT, int HEADS>
__global__ void k_gemm(const float* __restrict__ X, const float* __restrict__ W,
                       float* __restrict__ H,
                       const float* __restrict__ asrc, const float* __restrict__ adst,
                       float* __restrict__ as_out, float* __restrict__ ad_out) {
    constexpr int K  = 128;
    constexpr int TX = NOUT / 4;
    constexpr int MB = TY * NPT;              // nodes per block
    constexpr int G  = TX / HEADS;            // x-threads per head
    __shared__ float xs[MB][K];

    int tile0 = blockIdx.x * MB;
    int tid = threadIdx.y * TX + threadIdx.x;
    constexpr int NLOAD = MB * K / 4;
    for (int idx = tid; idx < NLOAD; idx += TX * TY) {
        int r = idx / (K / 4), c = idx % (K / 4);
        float4 v = make_float4(0.f, 0.f, 0.f, 0.f);
        int node = tile0 + r;
        if (node < N_NODES) v = ((const float4*)X)[node * (K / 4) + c];
        *(float4*)&xs[r][c * 4] = v;
    }
    __syncthreads();

    float4 acc[NPT];
#pragma unroll
    for (int p = 0; p < NPT; p++) acc[p] = make_float4(0.f, 0.f, 0.f, 0.f);
    int jx = threadIdx.x * 4;
    const float* Wp = W + jx;

#pragma unroll 4
    for (int k = 0; k < K; k++) {
        float4 w = *(const float4*)(Wp + k * NOUT);
#pragma unroll
        for (int p = 0; p < NPT; p++) {
            float xv = xs[threadIdx.y * NPT + p][k];
            acc[p].x += w.x * xv; acc[p].y += w.y * xv;
            acc[p].z += w.z * xv; acc[p].w += w.w * xv;
        }
    }

    float4 av = *(const float4*)&asrc[jx];
    float4 bv = *(const float4*)&adst[jx];
    int head = threadIdx.x / G;
#pragma unroll
    for (int p = 0; p < NPT; p++) {
        int node = tile0 + threadIdx.y * NPT + p;
        if (node < N_NODES) *(float4*)&H[node * NOUT + jx] = acc[p];
        float s = acc[p].x * av.x + acc[p].y * av.y + acc[p].z * av.z + acc[p].w * av.w;
        float d = acc[p].x * bv.x + acc[p].y * bv.y + acc[p].z * bv.z + acc[p].w * bv.w;
#pragma unroll
        for (int o = 1; o < G; o <<= 1) {
            s += __shfl_xor_sync(0xffffffffu, s, o);
            d += __shfl_xor_sync(0xffffffffu, d, o);
        }
        if ((threadIdx.x % G) == 0 && node < N_NODES) {
            as_out[node * HEADS + head] = s;
            ad_out[node * HEADS + head] = d;
        }
    }
}

// ---------------- layer-1: single-pass softmax + aggregate (warp per dst) ----
// x2 = elu( (Σ_e w_e * h1[src_e]) / (Σ_e w_e + eps) + b1 ),  w_e = exp(leaky(as+ad))
__global__ void k_agg1(const float* __restrict__ b1) {
    int gw = (blockIdx.x * blockDim.x + threadIdx.x) >> 5;
    int lane = threadIdx.x & 31;
    if (gw >= N_NODES) return;
    int beg = g_rowptr[gw], end = g_rowptr[gw + 1];
    int head = lane >> 2;                 // 4 lanes per head (16 cols/head)
    int col = lane * 4;
    float ad = g_ad1[gw * 8 + head];

    float4 acc = make_float4(0.f, 0.f, 0.f, 0.f);
    float sm = 0.f;
    int e = beg;
    for (; e + 3 < end; e += 4) {
        int s0 = g_srcsorted[e], s1 = g_srcsorted[e + 1];
        int s2 = g_srcsorted[e + 2], s3 = g_srcsorted[e + 3];
        float a0 = g_as1[s0 * 8 + head], a1 = g_as1[s1 * 8 + head];
        float a2 = g_as1[s2 * 8 + head], a3 = g_as1[s3 * 8 + head];
        float4 h0 = *(const float4*)&g_h1[s0 * 128 + col];
        float4 h1v = *(const float4*)&g_h1[s1 * 128 + col];
        float4 h2v = *(const float4*)&g_h1[s2 * 128 + col];
        float4 h3 = *(const float4*)&g_h1[s3 * 128 + col];
        float v0 = a0 + ad; v0 = v0 > 0.f ? v0 : NEG_SLOPE * v0;
        float v1 = a1 + ad; v1 = v1 > 0.f ? v1 : NEG_SLOPE * v1;
        float v2 = a2 + ad; v2 = v2 > 0.f ? v2 : NEG_SLOPE * v2;
        float v3 = a3 + ad; v3 = v3 > 0.f ? v3 : NEG_SLOPE * v3;
        float w0 = __expf(v0), w1 = __expf(v1), w2 = __expf(v2), w3 = __expf(v3);
        sm += (w0 + w1) + (w2 + w3);
        acc.x += w0 * h0.x + w1 * h1v.x + w2 * h2v.x + w3 * h3.x;
        acc.y += w0 * h0.y + w1 * h1v.y + w2 * h2v.y + w3 * h3.y;
        acc.z += w0 * h0.z + w1 * h1v.z + w2 * h2v.z + w3 * h3.z;
        acc.w += w0 * h0.w + w1 * h1v.w + w2 * h2v.w + w3 * h3.w;
    }
    for (; e < end; e++) {
        int s = g_srcsorted[e];
        float a = g_as1[s * 8 + head];
        float4 hv = *(const float4*)&g_h1[s * 128 + col];
        float v = a + ad; v = v > 0.f ? v : NEG_SLOPE * v;
        float w = __expf(v);
        sm += w;
        acc.x += w * hv.x; acc.y += w * hv.y;
        acc.z += w * hv.z; acc.w += w * hv.w;
    }

    float inv = 1.f / (sm + 1e-16f);
    float4 bb = *(const float4*)&b1[col];
    float o0 = acc.x * inv + bb.x, o1 = acc.y * inv + bb.y;
    float o2 = acc.z * inv + bb.z, o3 = acc.w * inv + bb.w;
    o0 = o0 > 0.f ? o0 : expm1f(o0);
    o1 = o1 > 0.f ? o1 : expm1f(o1);
    o2 = o2 > 0.f ? o2 : expm1f(o2);
    o3 = o3 > 0.f ? o3 : expm1f(o3);
    *(float4*)&g_x2[gw * 128 + col] = make_float4(o0, o1, o2, o3);
}

// ---------------- layer-2: single-pass softmax + aggregate + log_softmax ----
__global__ void k_agg2(const float* __restrict__ b2, float* __restrict__ out) {
    int gw = (blockIdx.x * blockDim.x + threadIdx.x) >> 5;
    int lane = threadIdx.x & 31;
    if (gw >= N_NODES) return;
    int beg = g_rowptr[gw], end = g_rowptr[gw + 1];
    float ad = g_ad2[gw];
    int col = lane * 2;

    float a0 = 0.f, a1 = 0.f, sm = 0.f;
    int e = beg;
    for (; e + 3 < end; e += 4) {
        int s0 = g_srcsorted[e], s1 = g_srcsorted[e + 1];
        int s2 = g_srcsorted[e + 2], s3 = g_srcsorted[e + 3];
        float x0 = g_as2[s0], x1 = g_as2[s1], x2 = g_as2[s2], x3 = g_as2[s3];
        float2 h0 = *(const float2*)&g_h2[s0 * 64 + col];
        float2 h1v = *(const float2*)&g_h2[s1 * 64 + col];
        float2 h2v = *(const float2*)&g_h2[s2 * 64 + col];
        float2 h3 = *(const float2*)&g_h2[s3 * 64 + col];
        float v0 = x0 + ad; v0 = v0 > 0.f ? v0 : NEG_SLOPE * v0;
        float v1 = x1 + ad; v1 = v1 > 0.f ? v1 : NEG_SLOPE * v1;
        float v2 = x2 + ad; v2 = v2 > 0.f ? v2 : NEG_SLOPE * v2;
        float v3 = x3 + ad; v3 = v3 > 0.f ? v3 : NEG_SLOPE * v3;
        float w0 = __expf(v0), w1 = __expf(v1), w2 = __expf(v2), w3 = __expf(v3);
        sm += (w0 + w1) + (w2 + w3);
        a0 += w0 * h0.x + w1 * h1v.x + w2 * h2v.x + w3 * h3.x;
        a1 += w0 * h0.y + w1 * h1v.y + w2 * h2v.y + w3 * h3.y;
    }
    for (; e < end; e++) {
        int s = g_srcsorted[e];
        float xv = g_as2[s];
        float2 hv = *(const float2*)&g_h2[s * 64 + col];
        float v = xv + ad; v = v > 0.f ? v : NEG_SLOPE * v;
        float w = __expf(v);
        sm += w;
        a0 += w * hv.x; a1 += w * hv.y;
    }

    float inv = 1.f / (sm + 1e-16f);
    float v0 = a0 * inv + b2[col], v1 = a1 * inv + b2[col + 1];
    v0 = v0 > 0.f ? v0 : expm1f(v0);
    v1 = v1 > 0.f ? v1 : expm1f(v1);

    // log_softmax over the 64 dims held by this warp
    float m = fmaxf(v0, v1);
#pragma unroll
    for (int o = 16; o; o >>= 1) m = fmaxf(m, __shfl_xor_sync(0xffffffffu, m, o));
    float es = expf(v0 - m) + expf(v1 - m);
#pragma unroll
    for (int o = 16; o; o >>= 1) es += __shfl_xor_sync(0xffffffffu, es, o);
    float lse = m + logf(es);
    *(float2*)&out[gw * 64 + col] = make_float2(v0 - lse, v1 - lse);
}

// ---------------- launch ----------------
extern "C" void kernel_launch(void* const* d_in, const int* in_sizes, int n_in,
                              void* d_out, int out_size) {
    const float* x      = (const float*)d_in[0];
    const void*  ei     = d_in[1];
    const float* W1     = (const float*)d_in[2];
    const float* a_src1 = (const float*)d_in[3];
    const float* a_dst1 = (const float*)d_in[4];
    const float* b1     = (const float*)d_in[5];
    const float* W2     = (const float*)d_in[6];
    const float* a_src2 = (const float*)d_in[7];
    const float* a_dst2 = (const float*)d_in[8];
    const float* b2     = (const float*)d_in[9];
    float* out = (float*)d_out;

    void *p_flag, *p_deg, *p_h1, *p_x2, *p_h2;
    void *p_as1, *p_ad1, *p_as2, *p_ad2;
    cudaGetSymbolAddress(&p_flag, g_flag32);
    cudaGetSymbolAddress(&p_deg, g_deg);
    cudaGetSymbolAddress(&p_h1, g_h1);
    cudaGetSymbolAddress(&p_x2, g_x2);
    cudaGetSymbolAddress(&p_h2, g_h2);
    cudaGetSymbolAddress(&p_as1, g_as1);
    cudaGetSymbolAddress(&p_ad1, g_ad1);
    cudaGetSymbolAddress(&p_as2, g_as2);
    cudaGetSymbolAddress(&p_ad2, g_ad2);

    cudaMemsetAsync(p_flag, 0, sizeof(int));
    cudaMemsetAsync(p_deg, 0, N_NODES * sizeof(int));

    k_detect<<<256, 256>>>((const unsigned int*)ei);
    k_convert<<<(E_TOT + 255) / 256, 256>>>(ei);
    k_scan<<<1, 1024>>>();
    k_scatter<<<(E_TOT + 255) / 256, 256>>>();

    // layer 1: gemm + fused alpha, then single-pass softmax-aggregate
    k_gemm<128, 8, 4, 8><<<(N_NODES + 31) / 32, dim3(32, 8)>>>(
        x, W1, (float*)p_h1, a_src1, a_dst1, (float*)p_as1, (float*)p_ad1);
    k_agg1<<<(N_NODES * 32 + 255) / 256, 256>>>(b1);

    // layer 2
    k_gemm<64, 16, 4, 1><<<(N_NODES + 63) / 64, dim3(16, 16)>>>(
        (const float*)p_x2, W2, (float*)p_h2, a_src2, a_dst2, (float*)p_as2, (float*)p_ad2);
    k_agg2<<<(N_NODES * 32 + 255) / 256, 256>>>(b2, out);
}